// round 8
// baseline (speedup 1.0000x reference)
#include <cuda_runtime.h>
#include <cuda_fp16.h>
#include <stdint.h>

#define B_  128
#define G_  20000
#define P_  4096
#define KT  32
#define NT  32
#define NCTA   (P_/NT)     // 128
#define NCHUNK (G_/KT)     // 625 exact
#define BN_EPS 1e-5f

// dynamic smem layout
#define WF32_STAGE 12288               // Wk 4KB | mapp 4KB | Wa 4KB
#define NSTAGE     8                   // fp32 W ring
#define WF16_BASE  (NSTAGE*WF32_STAGE) // 98304
#define W_ARR_B    2560                // fp16 [n][k] stride-20 array
#define WF16_STAGE (2*W_ARR_B)         // W + T, ring of 2
#define SMEM_DYN   (WF16_BASE + 2*WF16_STAGE + 256)   // ~108.8 KB
#define SHS 34                          // epilogue f32 row stride

__device__ __half g_Ah[B_ * G_];
__device__ float g_dpart[B_ * NCTA];

__device__ __forceinline__ uint32_t smem_u32(const void* p) {
    uint32_t a;
    asm("{ .reg .u64 t; cvta.to.shared.u64 t, %1; cvt.u32.u64 %0, t; }"
        : "=r"(a) : "l"(p));
    return a;
}
#define CPA16(dst, src) \
    asm volatile("cp.async.cg.shared.global [%0], [%1], 16;" :: "r"(dst), "l"(src))
#define CPA_COMMIT() asm volatile("cp.async.commit_group;")
#define CPA_WAIT6()  asm volatile("cp.async.wait_group 6;")

__device__ __forceinline__ void mma_f16(float* d, const uint32_t* a, uint32_t b0, uint32_t b1) {
    asm volatile(
        "mma.sync.aligned.m16n8k16.row.col.f32.f16.f16.f32 "
        "{%0,%1,%2,%3}, {%4,%5,%6,%7}, {%8,%9}, {%0,%1,%2,%3};"
        : "+f"(d[0]), "+f"(d[1]), "+f"(d[2]), "+f"(d[3])
        : "r"(a[0]), "r"(a[1]), "r"(a[2]), "r"(a[3]), "r"(b0), "r"(b1));
}

// ---------------- pre-convert A: fp32 -> fp16 global ----------------
__global__ __launch_bounds__(256) void presplit_kernel(const float* __restrict__ A) {
    int i4 = blockIdx.x * 256 + threadIdx.x;   // 640000 float4s exactly
    float4 v = ((const float4*)A)[i4];
    __half2 h0 = __floats2half2_rn(v.x, v.y);
    __half2 h1 = __floats2half2_rn(v.z, v.w);
    ((uint2*)g_Ah)[i4] = make_uint2(*(uint32_t*)&h0, *(uint32_t*)&h1);
}

// ---------------- fused main kernel ----------------
__global__ __launch_bounds__(256, 1) void bioxnet_fused_kernel(
    const float* __restrict__ mapp, const float* __restrict__ Wk,
    const float* __restrict__ Wa, const float* __restrict__ att_bias,
    const float* __restrict__ gamma, const float* __restrict__ beta,
    const float* __restrict__ dec_w,
    float* __restrict__ out_outcome, float* __restrict__ out_att)
{
    extern __shared__ __align__(16) char sp[];
    __shared__ float redS[8][NT], redQ[8][NT], s_mean[NT], s_rstd[NT];

    const int tid  = threadIdx.x;
    const int lane = tid & 31;
    const int wrp  = tid >> 5;
    const int gr   = lane >> 2;   // 0..7
    const int tc   = lane & 3;    // 0..3
    const int wr   = wrp >> 1;    // 0..3: 32-row group
    const int wc   = wrp & 1;     // 0..1: 16-col group
    const int col0 = blockIdx.x * NT;
    const uint32_t sb = smem_u32(sp);

    // A fragment LDG bases: 4 rows (u32-granular; G is even)
    const uint32_t* pA[4];
#pragma unroll
    for (int r = 0; r < 4; r++)
        pA[r] = (const uint32_t*)g_Ah + ((long)(wr * 32 + r * 8 + gr) * G_ >> 1) + tc;

    // W cp.async: thread -> row wkr0 = tid>>3, 16B unit wc0 = tid&7, one per array
    const int wkr0 = tid >> 3;
    const int wc0  = tid & 7;
    const long wgo = (long)wkr0 * P_ + col0 + wc0 * 4;
    const uint32_t wd0 = (uint32_t)(wkr0 * 128 + wc0 * 16);

#define CPA_W(chunk, st) do {                                             \
        uint32_t _b = sb + (uint32_t)(st) * WF32_STAGE + wd0;             \
        long _g = (long)(chunk) * KT * P_ + wgo;                          \
        CPA16(_b,         Wk   + _g);                                     \
        CPA16(_b + 4096,  mapp + _g);                                     \
        CPA16(_b + 8192,  Wa   + _g);                                     \
    } while (0)

    // CONV: thread -> col wn, 4 k rows starting wkq*4 (reads staged fp32)
    const int wn  = tid & 31;
    const int wkq = tid >> 5;   // 0..7

#define CONV_W(st32, st16) do {                                                   \
        const float* _f = (const float*)(sp + (st32) * WF32_STAGE);               \
        uint32_t* _w = (uint32_t*)(sp + WF16_BASE + (st16) * WF16_STAGE);         \
        uint32_t* _t = _w + (W_ARR_B / 4);                                        \
        const int _k0 = wkq * 4;                                                  \
        float _a0 = _f[(_k0    ) * 32 + wn], _m0 = _f[1024 + (_k0    ) * 32 + wn];\
        float _a1 = _f[(_k0 + 1) * 32 + wn], _m1 = _f[1024 + (_k0 + 1) * 32 + wn];\
        float _a2 = _f[(_k0 + 2) * 32 + wn], _m2 = _f[1024 + (_k0 + 2) * 32 + wn];\
        float _a3 = _f[(_k0 + 3) * 32 + wn], _m3 = _f[1024 + (_k0 + 3) * 32 + wn];\
        int _o = wn * 20 + wkq * 2;                                               \
        __half2 _p0 = __floats2half2_rn(_a0 * _m0, _a1 * _m1);                    \
        __half2 _p1 = __floats2half2_rn(_a2 * _m2, _a3 * _m3);                    \
        _w[_o] = *(uint32_t*)&_p0; _w[_o + 1] = *(uint32_t*)&_p1;                 \
        _a0 = _f[2048 + (_k0    ) * 32 + wn];                                     \
        _a1 = _f[2048 + (_k0 + 1) * 32 + wn];                                     \
        _a2 = _f[2048 + (_k0 + 2) * 32 + wn];                                     \
        _a3 = _f[2048 + (_k0 + 3) * 32 + wn];                                     \
        _p0 = __floats2half2_rn(_a0, _a1);                                        \
        _p1 = __floats2half2_rn(_a2, _a3);                                        \
        _t[_o] = *(uint32_t*)&_p0; _t[_o + 1] = *(uint32_t*)&_p1;                 \
    } while (0)

    float accH[2][2][4], accT[2][2][4];
#pragma unroll
    for (int rt = 0; rt < 2; rt++)
#pragma unroll
        for (int nt = 0; nt < 2; nt++)
#pragma unroll
            for (int i = 0; i < 4; i++) { accH[rt][nt][i] = 0.f; accT[rt][nt][i] = 0.f; }

    // -------- prologue: 7 W chunks in flight --------
#pragma unroll
    for (int c = 0; c < 7; c++) { CPA_W(c, c); CPA_COMMIT(); }

#pragma unroll 1
    for (int i = 0; i < NCHUNK; i++) {
        // A fragments for chunk i straight from L2 (use is ~2 barriers away)
        uint32_t areg[4][4];
        {
            const int kw = (i * KT) >> 1;   // u32 offset of chunk i
#pragma unroll
            for (int r = 0; r < 4; r++)
#pragma unroll
                for (int j = 0; j < 4; j++)
                    areg[r][j] = pA[r][kw + j * 4];
        }

        CPA_WAIT6();       // W(i) landed (7 pending -> 6)
        __syncthreads();   // all warps done CONV(i-1): stage (i+7)&7 reusable

        if (i + 7 < NCHUNK) CPA_W(i + 7, (i + 7) & 7);
        CPA_COMMIT();      // unconditional: keeps group count uniform

        CONV_W(i & 7, i & 1);
        __syncthreads();   // fp16 W/T visible before MMA

        const uint32_t* wW = (const uint32_t*)(sp + WF16_BASE + (i & 1) * WF16_STAGE);
        const uint32_t* wT = wW + (W_ARR_B / 4);

#pragma unroll
        for (int kh = 0; kh < 2; kh++) {
            uint32_t ah[2][4];
#pragma unroll
            for (int rt = 0; rt < 2; rt++) {
                ah[rt][0] = areg[rt * 2    ][kh * 2];
                ah[rt][1] = areg[rt * 2 + 1][kh * 2];
                ah[rt][2] = areg[rt * 2    ][kh * 2 + 1];
                ah[rt][3] = areg[rt * 2 + 1][kh * 2 + 1];
            }
#pragma unroll
            for (int nt = 0; nt < 2; nt++) {
                const int o = (wc * 16 + nt * 8 + gr) * 20 + kh * 8 + tc;
                uint32_t w0 = wW[o], w1 = wW[o + 4];
                uint32_t t0 = wT[o], t1 = wT[o + 4];
#pragma unroll
                for (int rt = 0; rt < 2; rt++) {
                    mma_f16(accH[rt][nt], ah[rt], w0, w1);
                    mma_f16(accT[rt][nt], ah[rt], t0, t1);
                }
            }
        }
    }
    __syncthreads();

    // ---- spill accumulators (GEMM bias omitted: cancels in BN mean-subtract) ----
    float* sH = (float*)sp;
    float* sT = (float*)(sp + 17408);
#pragma unroll
    for (int rt = 0; rt < 2; rt++) {
#pragma unroll
        for (int nt = 0; nt < 2; nt++) {
            const int row0 = wr * 32 + rt * 16 + gr;
            const int col  = wc * 16 + nt * 8 + 2 * tc;
            *(float2*)&sH[(row0    ) * SHS + col] = make_float2(accH[rt][nt][0], accH[rt][nt][1]);
            *(float2*)&sH[(row0 + 8) * SHS + col] = make_float2(accH[rt][nt][2], accH[rt][nt][3]);
            *(float2*)&sT[(row0    ) * SHS + col] = make_float2(accT[rt][nt][0], accT[rt][nt][1]);
            *(float2*)&sT[(row0 + 8) * SHS + col] = make_float2(accT[rt][nt][2], accT[rt][nt][3]);
        }
    }
    __syncthreads();

    // ---- batchnorm stats over all 128 rows (CTA-local) ----
    const int col = tid & 31;
    const int seg = tid >> 5;
    {
        float s = 0.f, q = 0.f;
#pragma unroll
        for (int r = 0; r < 16; r++) {
            float h = sH[(seg * 16 + r) * SHS + col];
            s += h; q += h * h;
        }
        redS[seg][col] = s;
        redQ[seg][col] = q;
    }
    __syncthreads();
    if (tid < 32) {
        float ss = 0.f, qq = 0.f;
#pragma unroll
        for (int i = 0; i < 8; i++) { ss += redS[i][tid]; qq += redQ[i][tid]; }
        float mean = ss * (1.0f / B_);
        float var  = qq * (1.0f / B_) - mean * mean;
        s_mean[tid] = mean;
        s_rstd[tid] = rsqrtf(var + BN_EPS);
    }
    __syncthreads();

    // ---- BN + tanh + sigmoid gate, outputs, decision partials ----
    const float mean = s_mean[col], rstd = s_rstd[col];
    const float gm = gamma[col0 + col], bt = beta[col0 + col];
    const float ab = att_bias[col0 + col], dw = dec_w[col0 + col];
#pragma unroll 4
    for (int r = 0; r < 16; r++) {
        int row = seg * 16 + r;
        float h  = sH[row * SHS + col];
        float hn = (h - mean) * rstd * gm + bt;
        float th = tanhf(hn);
        float z  = sT[row * SHS + col] + ab;
        float sg = 1.0f / (1.0f + __expf(-z));
        float o  = th * sg;
        long ofs = (long)row * P_ + col0 + col;
        out_outcome[ofs] = o;
        out_att[ofs]     = sg;
        float p = o * dw;
#pragma unroll
        for (int off = 16; off > 0; off >>= 1)
            p += __shfl_xor_sync(0xffffffffu, p, off);
        if (col == 0) g_dpart[row * NCTA + blockIdx.x] = p;
    }
}

__global__ __launch_bounds__(512) void bioxnet_decision_kernel(
    const float* __restrict__ dec_b, float* __restrict__ out_dec)
{
    __shared__ float red[4][B_];
    int t = threadIdx.x;
    int row = t >> 2;
    int seg = t & 3;
    const float4* p = (const float4*)(g_dpart + row * NCTA + seg * 32);
    float s = 0.f;
#pragma unroll
    for (int i = 0; i < 8; i++) {
        float4 v = p[i];
        s += v.x + v.y + v.z + v.w;
    }
    red[seg][row] = s;
    __syncthreads();
    if (t < B_) out_dec[t] = dec_b[0] + red[0][t] + red[1][t] + red[2][t] + red[3][t];
}

extern "C" void kernel_launch(void* const* d_in, const int* in_sizes, int n_in,
                              void* d_out, int out_size)
{
    (void)in_sizes; (void)n_in; (void)out_size;
    const float* A        = (const float*)d_in[0];
    const float* mapp     = (const float*)d_in[1];
    const float* Wk       = (const float*)d_in[2];
    // d_in[3] = bias: cancels exactly in batchnorm mean subtraction
    const float* Wa       = (const float*)d_in[4];
    const float* att_bias = (const float*)d_in[5];
    const float* gamma    = (const float*)d_in[6];
    const float* beta     = (const float*)d_in[7];
    const float* dec_w    = (const float*)d_in[8];
    const float* dec_b    = (const float*)d_in[9];

    float* out = (float*)d_out;
    float* out_outcome = out;
    float* out_dec     = out + (long)B_ * P_;
    float* out_att     = out + (long)B_ * P_ + B_;

    cudaFuncSetAttribute(bioxnet_fused_kernel,
                         cudaFuncAttributeMaxDynamicSharedMemorySize, SMEM_DYN);

    presplit_kernel<<<2500, 256>>>(A);
    bioxnet_fused_kernel<<<NCTA, 256, SMEM_DYN>>>(mapp, Wk, Wa, att_bias,
                                                  gamma, beta, dec_w,
                                                  out_outcome, out_att);
    bioxnet_decision_kernel<<<1, 512>>>(dec_b, out_dec);
}

// round 9
// speedup vs baseline: 1.2405x; 1.2405x over previous
#include <cuda_runtime.h>
#include <cuda_fp16.h>
#include <stdint.h>

#define B_  128
#define G_  20000
#define P_  4096
#define KT  32
#define NT  32
#define NCTA   (P_/NT)     // 128
#define NCHUNK (G_/KT)     // 625 exact
#define BN_EPS 1e-5f

// dynamic smem layout
#define A_ROWB     80                   // 32 halves + 16B pad -> u32 stride 20, conflict-free
#define A_STAGE_B  (128*A_ROWB)         // 10240; ring of 7
#define WF32_BASE  (7*A_STAGE_B)        // 71680
#define WF32_ROWB  144                  // 32 floats + 16B pad -> conflict-free conv reads
#define WF32_ARR   (32*WF32_ROWB)       // 4608 per array
#define WF32_STAGE (3*WF32_ARR)         // Wk | mapp | Wa = 13824; ring of 6
#define WF16_BASE  (WF32_BASE + 6*WF32_STAGE)   // 154624
#define W_ARR_B    2560                 // fp16 [n][k] stride-20 array
#define WF16_STAGE (2*W_ARR_B)          // W + T; ring of 2
#define SMEM_DYN   (WF16_BASE + 2*WF16_STAGE + 256)   // 165120 (~161 KB)
#define SHS 34                           // epilogue f32 row stride

__device__ __half g_Ah[B_ * G_];
__device__ float g_dpart[B_ * NCTA];

__device__ __forceinline__ uint32_t smem_u32(const void* p) {
    uint32_t a;
    asm("{ .reg .u64 t; cvta.to.shared.u64 t, %1; cvt.u32.u64 %0, t; }"
        : "=r"(a) : "l"(p));
    return a;
}
#define CPA16(dst, src) \
    asm volatile("cp.async.cg.shared.global [%0], [%1], 16;" :: "r"(dst), "l"(src))
#define CPA_COMMIT() asm volatile("cp.async.commit_group;")
#define CPA_WAIT5()  asm volatile("cp.async.wait_group 5;")

__device__ __forceinline__ void mma_f16(float* d, const uint32_t* a, uint32_t b0, uint32_t b1) {
    asm volatile(
        "mma.sync.aligned.m16n8k16.row.col.f32.f16.f16.f32 "
        "{%0,%1,%2,%3}, {%4,%5,%6,%7}, {%8,%9}, {%0,%1,%2,%3};"
        : "+f"(d[0]), "+f"(d[1]), "+f"(d[2]), "+f"(d[3])
        : "r"(a[0]), "r"(a[1]), "r"(a[2]), "r"(a[3]), "r"(b0), "r"(b1));
}

// ---------------- pre-convert A: fp32 -> fp16 global ----------------
__global__ __launch_bounds__(256) void presplit_kernel(const float* __restrict__ A) {
    int i4 = blockIdx.x * 256 + threadIdx.x;   // 640000 float4s exactly
    float4 v = ((const float4*)A)[i4];
    __half2 h0 = __floats2half2_rn(v.x, v.y);
    __half2 h1 = __floats2half2_rn(v.z, v.w);
    ((uint2*)g_Ah)[i4] = make_uint2(*(uint32_t*)&h0, *(uint32_t*)&h1);
}

// ---------------- fused main kernel ----------------
__global__ __launch_bounds__(256, 1) void bioxnet_fused_kernel(
    const float* __restrict__ mapp, const float* __restrict__ Wk,
    const float* __restrict__ Wa, const float* __restrict__ att_bias,
    const float* __restrict__ gamma, const float* __restrict__ beta,
    const float* __restrict__ dec_w,
    float* __restrict__ out_outcome, float* __restrict__ out_att)
{
    extern __shared__ __align__(16) char sp[];
    __shared__ float redS[8][NT], redQ[8][NT], s_mean[NT], s_rstd[NT];

    const int tid  = threadIdx.x;
    const int lane = tid & 31;
    const int wrp  = tid >> 5;
    const int gr   = lane >> 2;   // 0..7
    const int tc   = lane & 3;    // 0..3
    const int wr   = wrp >> 1;    // 0..3: 32-row group
    const int wc   = wrp & 1;     // 0..1: 16-col group
    const int col0 = blockIdx.x * NT;
    const uint32_t sb = smem_u32(sp);

    // A cp.async: thread -> (row = tid>>1, 2 of 4 16B units)
    const int arow = tid >> 1;
    const int auh  = (tid & 1) * 2;
    const __half* gH = g_Ah + (long)arow * G_ + auh * 8;
    const uint32_t ad0 = (uint32_t)(arow * A_ROWB + auh * 16);

#define CPA_A(chunk, st) do {                                 \
        uint32_t _b = sb + (uint32_t)(st) * A_STAGE_B + ad0;  \
        const __half* _h = gH + (chunk) * KT;                 \
        CPA16(_b, _h);  CPA16(_b + 16, _h + 8);               \
    } while (0)

    // W cp.async: thread -> row wkr0 = tid>>3, 16B unit wc0 = tid&7, one per array
    const int wkr0 = tid >> 3;
    const int wc0  = tid & 7;
    const long wgo = (long)wkr0 * P_ + col0 + wc0 * 4;
    const uint32_t wd0 = (uint32_t)(wkr0 * WF32_ROWB + wc0 * 16);

#define CPA_W(chunk, st) do {                                             \
        uint32_t _b = sb + WF32_BASE + (uint32_t)(st) * WF32_STAGE + wd0; \
        long _g = (long)(chunk) * KT * P_ + wgo;                          \
        CPA16(_b,                Wk   + _g);                              \
        CPA16(_b +   WF32_ARR,   mapp + _g);                              \
        CPA16(_b + 2*WF32_ARR,   Wa   + _g);                              \
    } while (0)

    // CONV: thread -> col wn, 4 k rows starting wkq*4 (reads staged fp32, pitch 36 words)
    const int wn  = tid & 31;
    const int wkq = tid >> 5;   // 0..7

#define CONV_W(st32, st16) do {                                                     \
        const float* _f = (const float*)(sp + WF32_BASE + (st32) * WF32_STAGE);     \
        uint32_t* _w = (uint32_t*)(sp + WF16_BASE + (st16) * WF16_STAGE);           \
        uint32_t* _t = _w + (W_ARR_B / 4);                                          \
        const int _k0 = wkq * 4;                                                    \
        float _a0 = _f[(_k0    ) * 36 + wn], _m0 = _f[1152 + (_k0    ) * 36 + wn];  \
        float _a1 = _f[(_k0 + 1) * 36 + wn], _m1 = _f[1152 + (_k0 + 1) * 36 + wn];  \
        float _a2 = _f[(_k0 + 2) * 36 + wn], _m2 = _f[1152 + (_k0 + 2) * 36 + wn];  \
        float _a3 = _f[(_k0 + 3) * 36 + wn], _m3 = _f[1152 + (_k0 + 3) * 36 + wn];  \
        int _o = wn * 20 + wkq * 2;                                                 \
        __half2 _p0 = __floats2half2_rn(_a0 * _m0, _a1 * _m1);                      \
        __half2 _p1 = __floats2half2_rn(_a2 * _m2, _a3 * _m3);                      \
        _w[_o] = *(uint32_t*)&_p0; _w[_o + 1] = *(uint32_t*)&_p1;                   \
        _a0 = _f[2304 + (_k0    ) * 36 + wn];                                       \
        _a1 = _f[2304 + (_k0 + 1) * 36 + wn];                                       \
        _a2 = _f[2304 + (_k0 + 2) * 36 + wn];                                       \
        _a3 = _f[2304 + (_k0 + 3) * 36 + wn];                                       \
        _p0 = __floats2half2_rn(_a0, _a1);                                          \
        _p1 = __floats2half2_rn(_a2, _a3);                                          \
        _t[_o] = *(uint32_t*)&_p0; _t[_o + 1] = *(uint32_t*)&_p1;                   \
    } while (0)

    float accH[2][2][4], accT[2][2][4];
#pragma unroll
    for (int rt = 0; rt < 2; rt++)
#pragma unroll
        for (int nt = 0; nt < 2; nt++)
#pragma unroll
            for (int i = 0; i < 4; i++) { accH[rt][nt][i] = 0.f; accT[rt][nt][i] = 0.f; }

    // MMA body for chunk j (A stage j%7, fp16 stage j&1)
#define MMA_CHUNK(j) do {                                                          \
        const uint32_t* aH = (const uint32_t*)(sp + ((j) % 7) * A_STAGE_B);        \
        const uint32_t* wW = (const uint32_t*)(sp + WF16_BASE + ((j) & 1) * WF16_STAGE); \
        const uint32_t* wT = wW + (W_ARR_B / 4);                                   \
        _Pragma("unroll")                                                          \
        for (int kh = 0; kh < 2; kh++) {                                           \
            uint32_t ah[2][4];                                                     \
            _Pragma("unroll")                                                      \
            for (int rt = 0; rt < 2; rt++) {                                       \
                const int o = (wr * 32 + rt * 16 + gr) * 20 + kh * 8 + tc;         \
                ah[rt][0] = aH[o];                                                 \
                ah[rt][1] = aH[o + 160];                                           \
                ah[rt][2] = aH[o + 4];                                             \
                ah[rt][3] = aH[o + 164];                                           \
            }                                                                      \
            _Pragma("unroll")                                                      \
            for (int nt = 0; nt < 2; nt++) {                                       \
                const int o = (wc * 16 + nt * 8 + gr) * 20 + kh * 8 + tc;          \
                uint32_t w0 = wW[o], w1 = wW[o + 4];                               \
                uint32_t t0 = wT[o], t1 = wT[o + 4];                               \
                _Pragma("unroll")                                                  \
                for (int rt = 0; rt < 2; rt++) {                                   \
                    mma_f16(accH[rt][nt], ah[rt], w0, w1);                         \
                    mma_f16(accT[rt][nt], ah[rt], t0, t1);                         \
                }                                                                  \
            }                                                                      \
        }                                                                          \
    } while (0)

    // -------- prologue: 5 unified groups (A+W per chunk) in flight --------
#pragma unroll
    for (int c = 0; c < 5; c++) { CPA_A(c, c); CPA_W(c, c); CPA_COMMIT(); }

#pragma unroll 1
    for (int i = 0; i < NCHUNK; i++) {
        __syncthreads();   // conv(i-1) + MMA(i-2)/conv reads complete everywhere

        if (i > 0) MMA_CHUNK(i - 1);   // overlaps with conv(i) below (no dependence)

        // prefetch chunk i+5: W stage (i-1)%6 (conv(i-1) done), A stage (i-2)%7 (MMA(i-2) done)
        if (i + 5 < NCHUNK) { CPA_A(i + 5, (i + 5) % 7); CPA_W(i + 5, (i + 5) % 6); }
        CPA_COMMIT();      // unconditional: uniform group count
        CPA_WAIT5();       // group i (A(i)+W(i)) landed

        CONV_W(i % 6, i & 1);
    }
    __syncthreads();
    MMA_CHUNK(NCHUNK - 1);
    __syncthreads();

    // ---- spill accumulators (GEMM bias omitted: cancels in BN mean-subtract) ----
    float* sH = (float*)sp;
    float* sT = (float*)(sp + 17408);
#pragma unroll
    for (int rt = 0; rt < 2; rt++) {
#pragma unroll
        for (int nt = 0; nt < 2; nt++) {
            const int row0 = wr * 32 + rt * 16 + gr;
            const int col  = wc * 16 + nt * 8 + 2 * tc;
            *(float2*)&sH[(row0    ) * SHS + col] = make_float2(accH[rt][nt][0], accH[rt][nt][1]);
            *(float2*)&sH[(row0 + 8) * SHS + col] = make_float2(accH[rt][nt][2], accH[rt][nt][3]);
            *(float2*)&sT[(row0    ) * SHS + col] = make_float2(accT[rt][nt][0], accT[rt][nt][1]);
            *(float2*)&sT[(row0 + 8) * SHS + col] = make_float2(accT[rt][nt][2], accT[rt][nt][3]);
        }
    }
    __syncthreads();

    // ---- batchnorm stats over all 128 rows (CTA-local) ----
    const int col = tid & 31;
    const int seg = tid >> 5;
    {
        float s = 0.f, q = 0.f;
#pragma unroll
        for (int r = 0; r < 16; r++) {
            float h = sH[(seg * 16 + r) * SHS + col];
            s += h; q += h * h;
        }
        redS[seg][col] = s;
        redQ[seg][col] = q;
    }
    __syncthreads();
    if (tid < 32) {
        float ss = 0.f, qq = 0.f;
#pragma unroll
        for (int i = 0; i < 8; i++) { ss += redS[i][tid]; qq += redQ[i][tid]; }
        float mean = ss * (1.0f / B_);
        float var  = qq * (1.0f / B_) - mean * mean;
        s_mean[tid] = mean;
        s_rstd[tid] = rsqrtf(var + BN_EPS);
    }
    __syncthreads();

    // ---- BN + tanh + sigmoid gate, outputs, decision partials ----
    const float mean = s_mean[col], rstd = s_rstd[col];
    const float gm = gamma[col0 + col], bt = beta[col0 + col];
    const float ab = att_bias[col0 + col], dw = dec_w[col0 + col];
#pragma unroll 4
    for (int r = 0; r < 16; r++) {
        int row = seg * 16 + r;
        float h  = sH[row * SHS + col];
        float hn = (h - mean) * rstd * gm + bt;
        float th = tanhf(hn);
        float z  = sT[row * SHS + col] + ab;
        float sg = 1.0f / (1.0f + __expf(-z));
        float o  = th * sg;
        long ofs = (long)row * P_ + col0 + col;
        out_outcome[ofs] = o;
        out_att[ofs]     = sg;
        float p = o * dw;
#pragma unroll
        for (int off = 16; off > 0; off >>= 1)
            p += __shfl_xor_sync(0xffffffffu, p, off);
        if (col == 0) g_dpart[row * NCTA + blockIdx.x] = p;
    }
}

__global__ __launch_bounds__(512) void bioxnet_decision_kernel(
    const float* __restrict__ dec_b, float* __restrict__ out_dec)
{
    __shared__ float red[4][B_];
    int t = threadIdx.x;
    int row = t >> 2;
    int seg = t & 3;
    const float4* p = (const float4*)(g_dpart + row * NCTA + seg * 32);
    float s = 0.f;
#pragma unroll
    for (int i = 0; i < 8; i++) {
        float4 v = p[i];
        s += v.x + v.y + v.z + v.w;
    }
    red[seg][row] = s;
    __syncthreads();
    if (t < B_) out_dec[t] = dec_b[0] + red[0][t] + red[1][t] + red[2][t] + red[3][t];
}

extern "C" void kernel_launch(void* const* d_in, const int* in_sizes, int n_in,
                              void* d_out, int out_size)
{
    (void)in_sizes; (void)n_in; (void)out_size;
    const float* A        = (const float*)d_in[0];
    const float* mapp     = (const float*)d_in[1];
    const float* Wk       = (const float*)d_in[2];
    // d_in[3] = bias: cancels exactly in batchnorm mean subtraction
    const float* Wa       = (const float*)d_in[4];
    const float* att_bias = (const float*)d_in[5];
    const float* gamma    = (const float*)d_in[6];
    const float* beta     = (const float*)d_in[7];
    const float* dec_w    = (const float*)d_in[8];
    const float* dec_b    = (const float*)d_in[9];

    float* out = (float*)d_out;
    float* out_outcome = out;
    float* out_dec     = out + (long)B_ * P_;
    float* out_att     = out + (long)B_ * P_ + B_;

    cudaFuncSetAttribute(bioxnet_fused_kernel,
                         cudaFuncAttributeMaxDynamicSharedMemorySize, SMEM_DYN);

    presplit_kernel<<<2500, 256>>>(A);
    bioxnet_fused_kernel<<<NCTA, 256, SMEM_DYN>>>(mapp, Wk, Wa, att_bias,
                                                  gamma, beta, dec_w,
                                                  out_outcome, out_att);
    bioxnet_decision_kernel<<<1, 512>>>(dec_b, out_dec);
}